// round 1
// baseline (speedup 1.0000x reference)
#include <cuda_runtime.h>
#include <cuda_bf16.h>
#include <cstdint>

// Problem dims (fixed by setup_inputs): B=4, S=4096, D=2048, H=5632
#define MTOK 16384
#define DDIM 2048
#define HDIM 5632
#define QEPS 1e-5f
#define RMSEPS 1e-6f

// ---------------- scratch (static device globals; no allocation) ----------------
__device__ __align__(16) int8_t g_xq[(size_t)MTOK * DDIM];     // quantized x
__device__ __align__(16) float  g_xdq[MTOK];                   // per-token dequant
__device__ __align__(16) int8_t g_w1q[(size_t)HDIM * DDIM];
__device__ __align__(16) int8_t g_w2q[(size_t)HDIM * DDIM];
__device__ __align__(16) int8_t g_w3q[(size_t)DDIM * HDIM];
__device__ __align__(16) float  g_wdq[3];                      // clip(mean|w|, eps)
__device__ __align__(16) float  g_wpart[3][1024];
__device__ __align__(16) float  g_gate[(size_t)MTOK * HDIM];   // gate, then h=silu(g)*u
__device__ __align__(16) float  g_up[(size_t)MTOK * HDIM];
__device__ __align__(16) int8_t g_hq[(size_t)MTOK * HDIM];
__device__ __align__(16) float  g_hdq[MTOK];

// ---------------- weight scale: deterministic two-stage |w| mean ----------------
__global__ void __launch_bounds__(256) wsum_partial(const float* __restrict__ w, int n, int slot) {
    float s = 0.f;
    for (int i = blockIdx.x * 256 + threadIdx.x; i < n; i += 1024 * 256)
        s += fabsf(w[i]);
    __shared__ float sm[256];
    sm[threadIdx.x] = s;
    __syncthreads();
    for (int o = 128; o; o >>= 1) {
        if (threadIdx.x < o) sm[threadIdx.x] += sm[threadIdx.x + o];
        __syncthreads();
    }
    if (threadIdx.x == 0) g_wpart[slot][blockIdx.x] = sm[0];
}

__global__ void __launch_bounds__(256) wsum_final(int slot, int n) {
    int t = threadIdx.x;
    float s = g_wpart[slot][t] + g_wpart[slot][t + 256] +
              g_wpart[slot][t + 512] + g_wpart[slot][t + 768];
    __shared__ float sm[256];
    sm[t] = s;
    __syncthreads();
    for (int o = 128; o; o >>= 1) {
        if (t < o) sm[t] += sm[t + o];
        __syncthreads();
    }
    if (t == 0) {
        float mean = sm[0] / (float)n;
        g_wdq[slot] = fmaxf(mean, QEPS);   // jnp.clip(mean, EPS)
    }
}

// ---------------- ternary weight quant ----------------
__global__ void __launch_bounds__(256) wquant(const float* __restrict__ w, int n, int slot) {
    int8_t* out = (slot == 0) ? g_w1q : (slot == 1) ? g_w2q : g_w3q;
    float sc = 1.0f / g_wdq[slot];
    int i = blockIdx.x * 256 + threadIdx.x;
    if (i < n) {
        int q = (int)rintf(w[i] * sc);
        q = max(-1, min(1, q));
        out[i] = (int8_t)q;
    }
}

// ---------------- fused RMSNorm + per-token int8 absmax quant ----------------
// which==0: input = xin (fp32), out g_xq/g_xdq.  which==1: input = g_gate (h), out g_hq/g_hdq.
__global__ void __launch_bounds__(256) act_quant(const float* __restrict__ xin, int which, int ncols) {
    const float* __restrict__ src = (which == 0) ? xin : g_gate;
    int8_t* __restrict__ q = (which == 0) ? g_xq : g_hq;
    float* __restrict__ dq = (which == 0) ? g_xdq : g_hdq;

    int row = blockIdx.x;
    size_t base = (size_t)row * ncols;
    int t = threadIdx.x;

    float ss = 0.f, am = 0.f;
    for (int i = t; i < ncols; i += 256) {
        float v = src[base + i];
        ss += v * v;
        am = fmaxf(am, fabsf(v));
    }
    __shared__ float s_ss[256], s_am[256];
    s_ss[t] = ss; s_am[t] = am;
    __syncthreads();
    for (int o = 128; o; o >>= 1) {
        if (t < o) {
            s_ss[t] += s_ss[t + o];
            s_am[t] = fmaxf(s_am[t], s_am[t + o]);
        }
        __syncthreads();
    }
    float r = rsqrtf(s_ss[0] / (float)ncols + RMSEPS);
    float anc = fmaxf(s_am[0] * r, QEPS);     // clip(absmax of normalized row, EPS)
    float sc = 127.0f / anc;
    float rs = r * sc;
    for (int i = t; i < ncols; i += 256) {
        int qi = (int)rintf(src[base + i] * rs);
        qi = max(-128, min(127, qi));
        q[base + i] = (int8_t)qi;
    }
    if (t == 0) dq[row] = anc * (1.0f / 127.0f);
}

// ---------------- int8 GEMM via mma.sync m16n8k32 ----------------
__device__ __forceinline__ void mma_s8(int* c, const int* a, const int* b) {
    asm volatile(
        "mma.sync.aligned.m16n8k32.row.col.s32.s8.s8.s32 "
        "{%0,%1,%2,%3}, {%4,%5,%6,%7}, {%8,%9}, {%0,%1,%2,%3};\n"
        : "+r"(c[0]), "+r"(c[1]), "+r"(c[2]), "+r"(c[3])
        : "r"(a[0]), "r"(a[1]), "r"(a[2]), "r"(a[3]), "r"(b[0]), "r"(b[1]));
}

// C[M,N] = (A[M,K] s8) x (B[N,K] s8)^T  scaled by adq[m]*wdq
// Block tile 128x128, 8 warps (2 in M x 4 in N), warp tile 64x32.
// which: 0 -> gate (A=xq,B=w1q), 1 -> up (A=xq,B=w2q), 2 -> out (A=hq,B=w3q,C=outext)
__global__ void __launch_bounds__(256, 1) gemm_s8(int which, float* outext,
                                                  int Ndim, int Kdim) {
    const int8_t* __restrict__ A;
    const int8_t* __restrict__ Bm;
    float* __restrict__ C;
    const float* __restrict__ adq;
    float wdq;
    if (which == 0)      { A = g_xq; Bm = g_w1q; C = g_gate; adq = g_xdq; wdq = g_wdq[0]; }
    else if (which == 1) { A = g_xq; Bm = g_w2q; C = g_up;   adq = g_xdq; wdq = g_wdq[1]; }
    else                 { A = g_hq; Bm = g_w3q; C = outext; adq = g_hdq; wdq = g_wdq[2]; }

    int lane = threadIdx.x & 31;
    int warp = threadIdx.x >> 5;
    int wm = warp & 1;       // 0..1
    int wn = warp >> 1;      // 0..3
    int m0 = blockIdx.y * 128 + wm * 64;
    int n0 = blockIdx.x * 128 + wn * 32;
    int g = lane >> 2;       // 0..7
    int t = lane & 3;        // 0..3

    int acc[4][4][4];
    #pragma unroll
    for (int mi = 0; mi < 4; mi++)
        #pragma unroll
        for (int ni = 0; ni < 4; ni++)
            #pragma unroll
            for (int j = 0; j < 4; j++) acc[mi][ni][j] = 0;

    const int8_t* Abase = A + (size_t)(m0 + g) * Kdim + t * 4;
    const int8_t* Bbase = Bm + (size_t)(n0 + g) * Kdim + t * 4;
    const size_t aRowStride = (size_t)16 * Kdim;
    const size_t bRowStride = (size_t)8 * Kdim;

    for (int k0 = 0; k0 < Kdim; k0 += 32) {
        int afr[4][4];
        #pragma unroll
        for (int mi = 0; mi < 4; mi++) {
            const int8_t* p = Abase + mi * aRowStride + k0;
            afr[mi][0] = *(const int*)(p);
            afr[mi][1] = *(const int*)(p + 8 * (size_t)Kdim);
            afr[mi][2] = *(const int*)(p + 16);
            afr[mi][3] = *(const int*)(p + 8 * (size_t)Kdim + 16);
        }
        int bfr[4][2];
        #pragma unroll
        for (int ni = 0; ni < 4; ni++) {
            const int8_t* p = Bbase + ni * bRowStride + k0;
            bfr[ni][0] = *(const int*)(p);
            bfr[ni][1] = *(const int*)(p + 16);
        }
        #pragma unroll
        for (int mi = 0; mi < 4; mi++)
            #pragma unroll
            for (int ni = 0; ni < 4; ni++)
                mma_s8(acc[mi][ni], afr[mi], bfr[ni]);
    }

    #pragma unroll
    for (int mi = 0; mi < 4; mi++) {
        int r0 = m0 + mi * 16 + g;
        float s0 = adq[r0] * wdq;
        float s1 = adq[r0 + 8] * wdq;
        #pragma unroll
        for (int ni = 0; ni < 4; ni++) {
            int c = n0 + ni * 8 + t * 2;
            float* C0 = C + (size_t)r0 * Ndim + c;
            float* C1 = C + (size_t)(r0 + 8) * Ndim + c;
            C0[0] = acc[mi][ni][0] * s0;
            C0[1] = acc[mi][ni][1] * s0;
            C1[0] = acc[mi][ni][2] * s1;
            C1[1] = acc[mi][ni][3] * s1;
        }
    }
}

// ---------------- swiglu elementwise: g_gate = silu(g_gate) * g_up ----------------
__global__ void __launch_bounds__(256) swiglu_mul(int n4) {
    int i = blockIdx.x * 256 + threadIdx.x;
    if (i < n4) {
        float4 gv = reinterpret_cast<float4*>(g_gate)[i];
        float4 uv = reinterpret_cast<float4*>(g_up)[i];
        float4 h;
        h.x = gv.x / (1.0f + expf(-gv.x)) * uv.x;
        h.y = gv.y / (1.0f + expf(-gv.y)) * uv.y;
        h.z = gv.z / (1.0f + expf(-gv.z)) * uv.z;
        h.w = gv.w / (1.0f + expf(-gv.w)) * uv.w;
        reinterpret_cast<float4*>(g_gate)[i] = h;
    }
}

// ---------------- launch ----------------
extern "C" void kernel_launch(void* const* d_in, const int* in_sizes, int n_in,
                              void* d_out, int out_size) {
    const float* x  = (const float*)d_in[0];
    const float* w1 = (const float*)d_in[1];
    const float* w2 = (const float*)d_in[2];
    const float* w3 = (const float*)d_in[3];
    float* out = (float*)d_out;

    const int nW = HDIM * DDIM;    // all three weight tensors have the same size
    for (int s = 0; s < 3; s++) {
        const float* w = (s == 0) ? w1 : (s == 1) ? w2 : w3;
        wsum_partial<<<1024, 256>>>(w, nW, s);
        wsum_final<<<1, 256>>>(s, nW);
        wquant<<<(nW + 255) / 256, 256>>>(w, nW, s);
    }

    // x -> rmsnorm -> int8
    act_quant<<<MTOK, 256>>>(x, 0, DDIM);

    // gate = xq @ w1q^T, up = xq @ w2q^T   [MTOK, HDIM]
    dim3 g1(HDIM / 128, MTOK / 128);
    gemm_s8<<<g1, 256>>>(0, nullptr, HDIM, DDIM);
    gemm_s8<<<g1, 256>>>(1, nullptr, HDIM, DDIM);

    // h = silu(gate) * up (in-place into g_gate)
    int n4 = (MTOK * HDIM) / 4;
    swiglu_mul<<<(n4 + 255) / 256, 256>>>(n4);

    // h -> rmsnorm -> int8
    act_quant<<<MTOK, 256>>>(nullptr, 1, HDIM);

    // out = hq @ w3q^T  [MTOK, DDIM]
    dim3 g3(DDIM / 128, MTOK / 128);
    gemm_s8<<<g3, 256>>>(2, out, DDIM, HDIM);
}

// round 2
// speedup vs baseline: 1.1710x; 1.1710x over previous
#include <cuda_runtime.h>
#include <cuda_bf16.h>
#include <cstdint>

// Problem dims (fixed by setup_inputs): B=4, S=4096, D=2048, H=5632
#define MTOK 16384
#define DDIM 2048
#define HDIM 5632
#define QEPS 1e-5f
#define RMSEPS 1e-6f

#define BM 128
#define BN 128
#define BK 64
#define STAGES 3

// ---------------- scratch (static device globals; no allocation) ----------------
__device__ __align__(16) int8_t g_xq[(size_t)MTOK * DDIM];     // quantized x
__device__ __align__(16) float  g_xdq[MTOK];                   // per-token dequant
__device__ __align__(16) int8_t g_w1q[(size_t)HDIM * DDIM];
__device__ __align__(16) int8_t g_w2q[(size_t)HDIM * DDIM];
__device__ __align__(16) int8_t g_w3q[(size_t)DDIM * HDIM];
__device__ __align__(16) float  g_wdq[3];                      // clip(mean|w|, eps)
__device__ __align__(16) float  g_wpart[3][1024];
__device__ __align__(16) float  g_gate[(size_t)MTOK * HDIM];
__device__ __align__(16) float  g_up[(size_t)MTOK * HDIM];
__device__ __align__(16) int8_t g_hq[(size_t)MTOK * HDIM];
__device__ __align__(16) float  g_hdq[MTOK];

// ---------------- weight scale: deterministic two-stage |w| mean ----------------
__global__ void __launch_bounds__(256) wsum_partial(const float* __restrict__ w, int n, int slot) {
    float s = 0.f;
    for (int i = blockIdx.x * 256 + threadIdx.x; i < n; i += 1024 * 256)
        s += fabsf(w[i]);
    __shared__ float sm[256];
    sm[threadIdx.x] = s;
    __syncthreads();
    for (int o = 128; o; o >>= 1) {
        if (threadIdx.x < o) sm[threadIdx.x] += sm[threadIdx.x + o];
        __syncthreads();
    }
    if (threadIdx.x == 0) g_wpart[slot][blockIdx.x] = sm[0];
}

__global__ void __launch_bounds__(256) wsum_final(int slot, int n) {
    int t = threadIdx.x;
    float s = g_wpart[slot][t] + g_wpart[slot][t + 256] +
              g_wpart[slot][t + 512] + g_wpart[slot][t + 768];
    __shared__ float sm[256];
    sm[t] = s;
    __syncthreads();
    for (int o = 128; o; o >>= 1) {
        if (t < o) sm[t] += sm[t + o];
        __syncthreads();
    }
    if (t == 0) {
        float mean = sm[0] / (float)n;
        g_wdq[slot] = fmaxf(mean, QEPS);
    }
}

// ---------------- ternary weight quant ----------------
__global__ void __launch_bounds__(256) wquant(const float* __restrict__ w, int n, int slot) {
    int8_t* out = (slot == 0) ? g_w1q : (slot == 1) ? g_w2q : g_w3q;
    float sc = 1.0f / g_wdq[slot];
    int i = blockIdx.x * 256 + threadIdx.x;
    if (i < n) {
        int q = (int)rintf(w[i] * sc);
        q = max(-1, min(1, q));
        out[i] = (int8_t)q;
    }
}

// ---------------- fused RMSNorm + per-token int8 absmax quant: x ----------------
__global__ void __launch_bounds__(256) actq_x(const float* __restrict__ x) {
    __shared__ float row[DDIM];
    __shared__ float red[256];
    int r = blockIdx.x;
    size_t base = (size_t)r * DDIM;
    int t = threadIdx.x;

    float ss = 0.f;
    for (int i = t; i < DDIM; i += 256) {
        float v = x[base + i];
        row[i] = v;
        ss += v * v;
    }
    red[t] = ss;
    __syncthreads();
    for (int o = 128; o; o >>= 1) {
        if (t < o) red[t] += red[t + o];
        __syncthreads();
    }
    float rr = rsqrtf(red[0] / (float)DDIM + RMSEPS);
    __syncthreads();

    float am = 0.f;
    for (int i = t; i < DDIM; i += 256) {
        float xn = row[i] * rr;
        am = fmaxf(am, fabsf(xn));
    }
    red[t] = am;
    __syncthreads();
    for (int o = 128; o; o >>= 1) {
        if (t < o) red[t] = fmaxf(red[t], red[t + o]);
        __syncthreads();
    }
    float anc = fmaxf(red[0], QEPS);
    float sc = 127.0f / anc;
    for (int i = t; i < DDIM; i += 256) {
        float xn = row[i] * rr;
        int qi = (int)rintf(xn * sc);
        qi = max(-128, min(127, qi));
        g_xq[base + i] = (int8_t)qi;
    }
    if (t == 0) g_xdq[r] = anc * (1.0f / 127.0f);
}

// ------- fused SwiGLU + RMSNorm + int8 quant: h = silu(gate)*up ----------
__global__ void __launch_bounds__(256) actq_h() {
    __shared__ float row[HDIM];
    __shared__ float red[256];
    int r = blockIdx.x;
    size_t base = (size_t)r * HDIM;
    int t = threadIdx.x;

    float ss = 0.f;
    for (int i = t; i < HDIM; i += 256) {
        float gv = g_gate[base + i];
        float uv = g_up[base + i];
        float h = gv / (1.0f + expf(-gv)) * uv;
        row[i] = h;
        ss += h * h;
    }
    red[t] = ss;
    __syncthreads();
    for (int o = 128; o; o >>= 1) {
        if (t < o) red[t] += red[t + o];
        __syncthreads();
    }
    float rr = rsqrtf(red[0] / (float)HDIM + RMSEPS);
    __syncthreads();

    float am = 0.f;
    for (int i = t; i < HDIM; i += 256) {
        float xn = row[i] * rr;
        am = fmaxf(am, fabsf(xn));
    }
    red[t] = am;
    __syncthreads();
    for (int o = 128; o; o >>= 1) {
        if (t < o) red[t] = fmaxf(red[t], red[t + o]);
        __syncthreads();
    }
    float anc = fmaxf(red[0], QEPS);
    float sc = 127.0f / anc;
    for (int i = t; i < HDIM; i += 256) {
        float xn = row[i] * rr;
        int qi = (int)rintf(xn * sc);
        qi = max(-128, min(127, qi));
        g_hq[base + i] = (int8_t)qi;
    }
    if (t == 0) g_hdq[r] = anc * (1.0f / 127.0f);
}

// ---------------- int8 GEMM: smem-staged, cp.async 3-stage pipeline ----------------
__device__ __forceinline__ void mma_s8(int* c, const int* a, const int* b) {
    asm volatile(
        "mma.sync.aligned.m16n8k32.row.col.s32.s8.s8.s32 "
        "{%0,%1,%2,%3}, {%4,%5,%6,%7}, {%8,%9}, {%0,%1,%2,%3};\n"
        : "+r"(c[0]), "+r"(c[1]), "+r"(c[2]), "+r"(c[3])
        : "r"(a[0]), "r"(a[1]), "r"(a[2]), "r"(a[3]), "r"(b[0]), "r"(b[1]));
}

// load one 128x64 A tile + 128x64 B tile into smem stage via cp.async (16B chunks)
__device__ __forceinline__ void stage_load(const int8_t* __restrict__ gA,
                                           const int8_t* __restrict__ gB,
                                           int Kdim, uint32_t sAu, uint32_t sBu, int tid) {
    #pragma unroll
    for (int j = 0; j < 2; j++) {
        int q = tid + j * 256;
        int row = q >> 2, c = q & 3;
        int cs = ((c ^ ((row >> 1) & 3)) << 4);
        const int8_t* pa = gA + (size_t)row * Kdim + c * 16;
        const int8_t* pb = gB + (size_t)row * Kdim + c * 16;
        uint32_t da = sAu + row * BK + cs;
        uint32_t db = sBu + row * BK + cs;
        asm volatile("cp.async.cg.shared.global [%0],[%1],16;\n" ::"r"(da), "l"(pa));
        asm volatile("cp.async.cg.shared.global [%0],[%1],16;\n" ::"r"(db), "l"(pb));
    }
}

// C[M,N] = (A[M,K] s8) x (B[N,K] s8)^T  scaled by adq[m]*wdq
// which: 0 -> gate (A=xq,B=w1q), 1 -> up (A=xq,B=w2q), 2 -> out (A=hq,B=w3q,C=outext)
__global__ void __launch_bounds__(256) gemm_s8(int which, float* outext, int Ndim, int Kdim) {
    const int8_t* __restrict__ A;
    const int8_t* __restrict__ Bm;
    float* __restrict__ C;
    const float* __restrict__ adq;
    float wdq;
    if (which == 0)      { A = g_xq; Bm = g_w1q; C = g_gate; adq = g_xdq; wdq = g_wdq[0]; }
    else if (which == 1) { A = g_xq; Bm = g_w2q; C = g_up;   adq = g_xdq; wdq = g_wdq[1]; }
    else                 { A = g_hq; Bm = g_w3q; C = outext; adq = g_hdq; wdq = g_wdq[2]; }

    __shared__ __align__(16) int8_t sA[STAGES][BM * BK];
    __shared__ __align__(16) int8_t sB[STAGES][BN * BK];

    int tid = threadIdx.x;
    int lane = tid & 31;
    int warp = tid >> 5;
    int wm = warp & 1;
    int wn = warp >> 1;
    int g = lane >> 2;
    int t = lane & 3;
    int m0blk = blockIdx.y * BM;
    int n0blk = blockIdx.x * BN;

    uint32_t sAu = (uint32_t)__cvta_generic_to_shared(&sA[0][0]);
    uint32_t sBu = (uint32_t)__cvta_generic_to_shared(&sB[0][0]);

    const int NT = Kdim / BK;

    // prologue: fill all stages
    #pragma unroll
    for (int i = 0; i < STAGES; i++) {
        stage_load(A + (size_t)m0blk * Kdim + i * BK,
                   Bm + (size_t)n0blk * Kdim + i * BK,
                   Kdim, sAu + i * (BM * BK), sBu + i * (BN * BK), tid);
        asm volatile("cp.async.commit_group;\n");
    }

    // per-thread fragment addressing (byte offsets within a stage)
    int aoff0[4], aoff1[4], asw0[4], asw1[4];
    #pragma unroll
    for (int mi = 0; mi < 4; mi++) {
        int r0 = wm * 64 + mi * 16 + g;
        int r1 = r0 + 8;
        aoff0[mi] = r0 * BK + t * 4;
        aoff1[mi] = r1 * BK + t * 4;
        asw0[mi] = ((r0 >> 1) & 3) << 4;
        asw1[mi] = ((r1 >> 1) & 3) << 4;
    }
    int boff[4], bsw[4];
    #pragma unroll
    for (int ni = 0; ni < 4; ni++) {
        int rn = wn * 32 + ni * 8 + g;
        boff[ni] = rn * BK + t * 4;
        bsw[ni] = ((rn >> 1) & 3) << 4;
    }

    int acc[4][4][4];
    #pragma unroll
    for (int mi = 0; mi < 4; mi++)
        #pragma unroll
        for (int ni = 0; ni < 4; ni++)
            #pragma unroll
            for (int j = 0; j < 4; j++) acc[mi][ni][j] = 0;

    for (int kt = 0; kt < NT; kt++) {
        int st = kt % STAGES;
        asm volatile("cp.async.wait_group 2;\n" ::: "memory");
        __syncthreads();

        const int8_t* bA = &sA[st][0];
        const int8_t* bB = &sB[st][0];

        #pragma unroll
        for (int ks = 0; ks < 2; ks++) {
            int c0 = (ks * 2) << 4;      // byte offset of 16B chunk (low half)
            int c1 = (ks * 2 + 1) << 4;  // high half
            int afr[4][4];
            #pragma unroll
            for (int mi = 0; mi < 4; mi++) {
                afr[mi][0] = *(const int*)(bA + aoff0[mi] + (c0 ^ asw0[mi]));
                afr[mi][1] = *(const int*)(bA + aoff1[mi] + (c0 ^ asw1[mi]));
                afr[mi][2] = *(const int*)(bA + aoff0[mi] + (c1 ^ asw0[mi]));
                afr[mi][3] = *(const int*)(bA + aoff1[mi] + (c1 ^ asw1[mi]));
            }
            int bfr[4][2];
            #pragma unroll
            for (int ni = 0; ni < 4; ni++) {
                bfr[ni][0] = *(const int*)(bB + boff[ni] + (c0 ^ bsw[ni]));
                bfr[ni][1] = *(const int*)(bB + boff[ni] + (c1 ^ bsw[ni]));
            }
            #pragma unroll
            for (int mi = 0; mi < 4; mi++)
                #pragma unroll
                for (int ni = 0; ni < 4; ni++)
                    mma_s8(acc[mi][ni], afr[mi], bfr[ni]);
        }

        __syncthreads();
        int nkt = kt + STAGES;
        if (nkt < NT) {
            stage_load(A + (size_t)m0blk * Kdim + nkt * BK,
                       Bm + (size_t)n0blk * Kdim + nkt * BK,
                       Kdim, sAu + st * (BM * BK), sBu + st * (BN * BK), tid);
        }
        asm volatile("cp.async.commit_group;\n");
    }

    // epilogue
    #pragma unroll
    for (int mi = 0; mi < 4; mi++) {
        int r0 = m0blk + wm * 64 + mi * 16 + g;
        float s0 = adq[r0] * wdq;
        float s1 = adq[r0 + 8] * wdq;
        #pragma unroll
        for (int ni = 0; ni < 4; ni++) {
            int c = n0blk + wn * 32 + ni * 8 + t * 2;
            float* C0 = C + (size_t)r0 * Ndim + c;
            float* C1 = C + (size_t)(r0 + 8) * Ndim + c;
            C0[0] = acc[mi][ni][0] * s0;
            C0[1] = acc[mi][ni][1] * s0;
            C1[0] = acc[mi][ni][2] * s1;
            C1[1] = acc[mi][ni][3] * s1;
        }
    }
}

// ---------------- launch ----------------
extern "C" void kernel_launch(void* const* d_in, const int* in_sizes, int n_in,
                              void* d_out, int out_size) {
    const float* x  = (const float*)d_in[0];
    const float* w1 = (const float*)d_in[1];
    const float* w2 = (const float*)d_in[2];
    const float* w3 = (const float*)d_in[3];
    float* out = (float*)d_out;

    const int nW = HDIM * DDIM;
    for (int s = 0; s < 3; s++) {
        const float* w = (s == 0) ? w1 : (s == 1) ? w2 : w3;
        wsum_partial<<<1024, 256>>>(w, nW, s);
        wsum_final<<<1, 256>>>(s, nW);
        wquant<<<(nW + 255) / 256, 256>>>(w, nW, s);
    }

    // x -> rmsnorm -> int8
    actq_x<<<MTOK, 256>>>(x);

    // gate = xq @ w1q^T, up = xq @ w2q^T   [MTOK, HDIM]
    dim3 g1(HDIM / BN, MTOK / BM);
    gemm_s8<<<g1, 256>>>(0, nullptr, HDIM, DDIM);
    gemm_s8<<<g1, 256>>>(1, nullptr, HDIM, DDIM);

    // h = silu(gate)*up -> rmsnorm -> int8 (fused)
    actq_h<<<MTOK, 256>>>();

    // out = hq @ w3q^T  [MTOK, DDIM]
    dim3 g3(DDIM / BN, MTOK / BM);
    gemm_s8<<<g3, 256>>>(2, out, DDIM, HDIM);
}

// round 3
// speedup vs baseline: 1.1819x; 1.0093x over previous
#include <cuda_runtime.h>
#include <cuda.h>
#include <cuda_bf16.h>
#include <cstdint>

// Problem dims (fixed by setup_inputs): B=4, S=4096, D=2048, H=5632
#define MTOK 16384
#define DDIM 2048
#define HDIM 5632
#define QEPS 1e-5f
#define RMSEPS 1e-6f

#define BM 128
#define BN 128
#define BK 64
#define STAGES 3

// ---------------- scratch (static device globals; no allocation) ----------------
__device__ __align__(16) int8_t g_xq[(size_t)MTOK * DDIM];
__device__ __align__(16) float  g_xdq[MTOK];
__device__ __align__(16) int8_t g_w1q[(size_t)HDIM * DDIM];
__device__ __align__(16) int8_t g_w2q[(size_t)HDIM * DDIM];
__device__ __align__(16) int8_t g_w3q[(size_t)DDIM * HDIM];
__device__ __align__(16) float  g_wdq[3];
__device__ __align__(16) float  g_wpart[3][1024];
__device__ __align__(16) float  g_gate[(size_t)MTOK * HDIM];
__device__ __align__(16) float  g_up[(size_t)MTOK * HDIM];
__device__ __align__(16) int8_t g_hq[(size_t)MTOK * HDIM];
__device__ __align__(16) float  g_hdq[MTOK];

// ---------------- weight scale: deterministic two-stage |w| mean (all 3 fused) ----------------
__global__ void __launch_bounds__(256) wsum_partial_all(const float* __restrict__ w1,
                                                        const float* __restrict__ w2,
                                                        const float* __restrict__ w3, int n) {
    int slot = blockIdx.x >> 10;
    int blk = blockIdx.x & 1023;
    const float* w = (slot == 0) ? w1 : (slot == 1) ? w2 : w3;
    float s = 0.f;
    for (int i = blk * 256 + threadIdx.x; i < n; i += 1024 * 256)
        s += fabsf(w[i]);
    __shared__ float sm[256];
    sm[threadIdx.x] = s;
    __syncthreads();
    for (int o = 128; o; o >>= 1) {
        if (threadIdx.x < o) sm[threadIdx.x] += sm[threadIdx.x + o];
        __syncthreads();
    }
    if (threadIdx.x == 0) g_wpart[slot][blk] = sm[0];
}

__global__ void __launch_bounds__(256) wsum_final_all(int n) {
    int slot = blockIdx.x;
    int t = threadIdx.x;
    float s = g_wpart[slot][t] + g_wpart[slot][t + 256] +
              g_wpart[slot][t + 512] + g_wpart[slot][t + 768];
    __shared__ float sm[256];
    sm[t] = s;
    __syncthreads();
    for (int o = 128; o; o >>= 1) {
        if (t < o) sm[t] += sm[t + o];
        __syncthreads();
    }
    if (t == 0) {
        float mean = sm[0] / (float)n;
        g_wdq[slot] = fmaxf(mean, QEPS);
    }
}

// ---------------- ternary weight quant (all 3 fused) ----------------
__global__ void __launch_bounds__(256) wquant_all(const float* __restrict__ w1,
                                                  const float* __restrict__ w2,
                                                  const float* __restrict__ w3, int n) {
    int slot = blockIdx.y;
    const float* w = (slot == 0) ? w1 : (slot == 1) ? w2 : w3;
    int8_t* out = (slot == 0) ? g_w1q : (slot == 1) ? g_w2q : g_w3q;
    float sc = 1.0f / g_wdq[slot];
    int i = blockIdx.x * 256 + threadIdx.x;
    if (i < n) {
        int q = (int)rintf(w[i] * sc);
        q = max(-1, min(1, q));
        out[i] = (int8_t)q;
    }
}

// ---------------- fused RMSNorm + per-token int8 absmax quant: x ----------------
__global__ void __launch_bounds__(256) actq_x(const float* __restrict__ x) {
    __shared__ float row[DDIM];
    __shared__ float red[256];
    int r = blockIdx.x;
    size_t base = (size_t)r * DDIM;
    int t = threadIdx.x;

    float ss = 0.f;
    for (int i = t; i < DDIM; i += 256) {
        float v = x[base + i];
        row[i] = v;
        ss += v * v;
    }
    red[t] = ss;
    __syncthreads();
    for (int o = 128; o; o >>= 1) {
        if (t < o) red[t] += red[t + o];
        __syncthreads();
    }
    float rr = rsqrtf(red[0] / (float)DDIM + RMSEPS);
    __syncthreads();

    float am = 0.f;
    for (int i = t; i < DDIM; i += 256) {
        float xn = row[i] * rr;
        am = fmaxf(am, fabsf(xn));
    }
    red[t] = am;
    __syncthreads();
    for (int o = 128; o; o >>= 1) {
        if (t < o) red[t] = fmaxf(red[t], red[t + o]);
        __syncthreads();
    }
    float anc = fmaxf(red[0], QEPS);
    float sc = 127.0f / anc;
    for (int i = t; i < DDIM; i += 256) {
        float xn = row[i] * rr;
        int qi = (int)rintf(xn * sc);
        qi = max(-128, min(127, qi));
        g_xq[base + i] = (int8_t)qi;
    }
    if (t == 0) g_xdq[r] = anc * (1.0f / 127.0f);
}

// ------- fused SwiGLU + RMSNorm + int8 quant: h = silu(gate)*up ----------
__global__ void __launch_bounds__(256) actq_h() {
    __shared__ float row[HDIM];
    __shared__ float red[256];
    int r = blockIdx.x;
    size_t base = (size_t)r * HDIM;
    int t = threadIdx.x;

    float ss = 0.f;
    for (int i = t; i < HDIM; i += 256) {
        float gv = g_gate[base + i];
        float uv = g_up[base + i];
        float h = gv / (1.0f + expf(-gv)) * uv;
        row[i] = h;
        ss += h * h;
    }
    red[t] = ss;
    __syncthreads();
    for (int o = 128; o; o >>= 1) {
        if (t < o) red[t] += red[t + o];
        __syncthreads();
    }
    float rr = rsqrtf(red[0] / (float)HDIM + RMSEPS);
    __syncthreads();

    float am = 0.f;
    for (int i = t; i < HDIM; i += 256) {
        float xn = row[i] * rr;
        am = fmaxf(am, fabsf(xn));
    }
    red[t] = am;
    __syncthreads();
    for (int o = 128; o; o >>= 1) {
        if (t < o) red[t] = fmaxf(red[t], red[t + o]);
        __syncthreads();
    }
    float anc = fmaxf(red[0], QEPS);
    float sc = 127.0f / anc;
    for (int i = t; i < HDIM; i += 256) {
        float xn = row[i] * rr;
        int qi = (int)rintf(xn * sc);
        qi = max(-128, min(127, qi));
        g_hq[base + i] = (int8_t)qi;
    }
    if (t == 0) g_hdq[r] = anc * (1.0f / 127.0f);
}

// ---------------- int8 GEMM: TMA-staged (SW64), 3-stage mbarrier pipeline ----------------
__device__ __forceinline__ void mma_s8(int* c, const int* a, const int* b) {
    asm volatile(
        "mma.sync.aligned.m16n8k32.row.col.s32.s8.s8.s32 "
        "{%0,%1,%2,%3}, {%4,%5,%6,%7}, {%8,%9}, {%0,%1,%2,%3};\n"
        : "+r"(c[0]), "+r"(c[1]), "+r"(c[2]), "+r"(c[3])
        : "r"(a[0]), "r"(a[1]), "r"(a[2]), "r"(a[3]), "r"(b[0]), "r"(b[1]));
}

#define MBAR_INIT(a, c) \
    asm volatile("mbarrier.init.shared.b64 [%0], %1;" ::"r"(a), "r"(c) : "memory")
#define MBAR_EXPECT(a, b) \
    asm volatile("mbarrier.arrive.expect_tx.shared.b64 _, [%0], %1;" ::"r"(a), "r"(b) : "memory")
#define TMA2D(dst, map, cx, cy, mb) \
    asm volatile("cp.async.bulk.tensor.2d.shared::cta.global.tile.mbarrier::complete_tx::bytes " \
                 "[%0], [%1, {%2, %3}], [%4];" ::"r"(dst), "l"(map), "r"(cx), "r"(cy), "r"(mb) : "memory")

__device__ __forceinline__ void mbar_wait(uint32_t addr, uint32_t parity) {
    uint32_t done;
    asm volatile(
        "{\n\t.reg .pred p;\n\t"
        "mbarrier.try_wait.parity.acquire.cta.shared::cta.b64 p, [%1], %2;\n\t"
        "selp.b32 %0, 1, 0, p;\n\t}"
        : "=r"(done) : "r"(addr), "r"(parity) : "memory");
    if (!done) {
        asm volatile(
            "{\n\t.reg .pred P1;\n\t"
            "WL_%=:\n\t"
            "mbarrier.try_wait.parity.acquire.cta.shared::cta.b64 P1, [%0], %1, 0x989680;\n\t"
            "@P1 bra.uni WD_%=;\n\t"
            "bra.uni WL_%=;\n\t"
            "WD_%=:\n\t}"
            ::"r"(addr), "r"(parity) : "memory");
    }
}

// C[M,N] = (A[M,K] s8) x (B[N,K] s8)^T  scaled by adq[m]*wdq
// which: 0 -> gate, 1 -> up, 2 -> out (C=outext)
__global__ void __launch_bounds__(256) gemm_s8(int which, float* outext, int Ndim, int Kdim,
                                               const __grid_constant__ CUtensorMap tmA,
                                               const __grid_constant__ CUtensorMap tmB) {
    float* __restrict__ C;
    const float* __restrict__ adq;
    float wdq;
    if (which == 0)      { C = g_gate; adq = g_xdq; wdq = g_wdq[0]; }
    else if (which == 1) { C = g_up;   adq = g_xdq; wdq = g_wdq[1]; }
    else                 { C = outext; adq = g_hdq; wdq = g_wdq[2]; }

    __shared__ __align__(1024) int8_t sA[STAGES][BM * BK];
    __shared__ __align__(1024) int8_t sB[STAGES][BN * BK];
    __shared__ __align__(8) uint64_t mbar[STAGES];

    int tid = threadIdx.x;
    int lane = tid & 31;
    int warp = tid >> 5;
    int wm = warp & 1;
    int wn = warp >> 1;
    int g = lane >> 2;
    int t = lane & 3;
    int m0blk = blockIdx.y * BM;
    int n0blk = blockIdx.x * BN;

    uint32_t sAu = (uint32_t)__cvta_generic_to_shared(&sA[0][0]);
    uint32_t sBu = (uint32_t)__cvta_generic_to_shared(&sB[0][0]);
    uint32_t mbu = (uint32_t)__cvta_generic_to_shared(&mbar[0]);

    const int NT = Kdim / BK;

    if (tid == 0) {
        #pragma unroll
        for (int s = 0; s < STAGES; s++) MBAR_INIT(mbu + s * 8, 1);
        asm volatile("fence.proxy.async.shared::cta;" ::: "memory");
    }
    __syncthreads();

    if (tid == 0) {
        #pragma unroll
        for (int s = 0; s < STAGES; s++) {
            MBAR_EXPECT(mbu + s * 8, (BM + BN) * BK);
            TMA2D(sAu + s * (BM * BK), &tmA, s * BK, m0blk, mbu + s * 8);
            TMA2D(sBu + s * (BN * BK), &tmB, s * BK, n0blk, mbu + s * 8);
        }
    }

    // per-thread fragment byte offsets within a stage (SW64 swizzle = chunk ^ ((row>>1)&3))
    int aoff0[4], aoff1[4], asw0[4], asw1[4];
    #pragma unroll
    for (int mi = 0; mi < 4; mi++) {
        int r0 = wm * 64 + mi * 16 + g;
        int r1 = r0 + 8;
        aoff0[mi] = r0 * BK + t * 4;
        aoff1[mi] = r1 * BK + t * 4;
        asw0[mi] = ((r0 >> 1) & 3) << 4;
        asw1[mi] = ((r1 >> 1) & 3) << 4;
    }
    int boff[4], bsw[4];
    #pragma unroll
    for (int ni = 0; ni < 4; ni++) {
        int rn = wn * 32 + ni * 8 + g;
        boff[ni] = rn * BK + t * 4;
        bsw[ni] = ((rn >> 1) & 3) << 4;
    }

    int acc[4][4][4];
    #pragma unroll
    for (int mi = 0; mi < 4; mi++)
        #pragma unroll
        for (int ni = 0; ni < 4; ni++)
            #pragma unroll
            for (int j = 0; j < 4; j++) acc[mi][ni][j] = 0;

    int phase = 0;
    for (int kt = 0; kt < NT; kt++) {
        int st = kt % STAGES;
        mbar_wait(mbu + st * 8, phase);
        if (st == STAGES - 1) phase ^= 1;

        const int8_t* bA = &sA[st][0];
        const int8_t* bB = &sB[st][0];

        #pragma unroll
        for (int ks = 0; ks < 2; ks++) {
            int c0 = (ks * 2) << 4;
            int c1 = (ks * 2 + 1) << 4;
            int afr[4][4];
            #pragma unroll
            for (int mi = 0; mi < 4; mi++) {
                afr[mi][0] = *(const int*)(bA + aoff0[mi] + (c0 ^ asw0[mi]));
                afr[mi][1] = *(const int*)(bA + aoff1[mi] + (c0 ^ asw1[mi]));
                afr[mi][2] = *(const int*)(bA + aoff0[mi] + (c1 ^ asw0[mi]));
                afr[mi][3] = *(const int*)(bA + aoff1[mi] + (c1 ^ asw1[mi]));
            }
            int bfr[4][2];
            #pragma unroll
            for (int ni = 0; ni < 4; ni++) {
                bfr[ni][0] = *(const int*)(bB + boff[ni] + (c0 ^ bsw[ni]));
                bfr[ni][1] = *(const int*)(bB + boff[ni] + (c1 ^ bsw[ni]));
            }
            #pragma unroll
            for (int mi = 0; mi < 4; mi++)
                #pragma unroll
                for (int ni = 0; ni < 4; ni++)
                    mma_s8(acc[mi][ni], afr[mi], bfr[ni]);
        }

        __syncthreads();
        int nkt = kt + STAGES;
        if (tid == 0 && nkt < NT) {
            MBAR_EXPECT(mbu + st * 8, (BM + BN) * BK);
            TMA2D(sAu + st * (BM * BK), &tmA, nkt * BK, m0blk, mbu + st * 8);
            TMA2D(sBu + st * (BN * BK), &tmB, nkt * BK, n0blk, mbu + st * 8);
        }
    }

    // epilogue
    #pragma unroll
    for (int mi = 0; mi < 4; mi++) {
        int r0 = m0blk + wm * 64 + mi * 16 + g;
        float s0 = adq[r0] * wdq;
        float s1 = adq[r0 + 8] * wdq;
        #pragma unroll
        for (int ni = 0; ni < 4; ni++) {
            int c = n0blk + wn * 32 + ni * 8 + t * 2;
            float* C0 = C + (size_t)r0 * Ndim + c;
            float* C1 = C + (size_t)(r0 + 8) * Ndim + c;
            C0[0] = acc[mi][ni][0] * s0;
            C0[1] = acc[mi][ni][1] * s0;
            C1[0] = acc[mi][ni][2] * s1;
            C1[1] = acc[mi][ni][3] * s1;
        }
    }
}

// ---------------- host: tensormap encode via runtime-resolved driver entry ----------------
typedef CUresult (*PFN_tmEncode)(CUtensorMap*, CUtensorMapDataType, cuuint32_t, void*,
                                 const cuuint64_t*, const cuuint64_t*, const cuuint32_t*,
                                 const cuuint32_t*, CUtensorMapInterleave, CUtensorMapSwizzle,
                                 CUtensorMapL2promotion, CUtensorMapFloatOOBfill);

static PFN_tmEncode get_encoder() {
    void* fp = nullptr;
    cudaDriverEntryPointQueryResult qr;
#if CUDART_VERSION >= 12050
    cudaGetDriverEntryPointByVersion("cuTensorMapEncodeTiled", &fp, 12000, cudaEnableDefault, &qr);
#else
    cudaGetDriverEntryPoint("cuTensorMapEncodeTiled", &fp, cudaEnableDefault, &qr);
#endif
    return (PFN_tmEncode)fp;
}

static void make_map(PFN_tmEncode enc, CUtensorMap* m, void* base, uint64_t kdim, uint64_t rows) {
    cuuint64_t dims[2] = {kdim, rows};
    cuuint64_t strides[1] = {kdim};           // bytes (elem = 1B)
    cuuint32_t box[2] = {BK, BM};             // 64 x 128 tile
    cuuint32_t es[2] = {1, 1};
    enc(m, CU_TENSOR_MAP_DATA_TYPE_UINT8, 2, base, dims, strides, box, es,
        CU_TENSOR_MAP_INTERLEAVE_NONE, CU_TENSOR_MAP_SWIZZLE_64B,
        CU_TENSOR_MAP_L2_PROMOTION_L2_128B, CU_TENSOR_MAP_FLOAT_OOB_FILL_NONE);
}

// ---------------- launch ----------------
extern "C" void kernel_launch(void* const* d_in, const int* in_sizes, int n_in,
                              void* d_out, int out_size) {
    const float* x  = (const float*)d_in[0];
    const float* w1 = (const float*)d_in[1];
    const float* w2 = (const float*)d_in[2];
    const float* w3 = (const float*)d_in[3];
    float* out = (float*)d_out;

    PFN_tmEncode enc = get_encoder();
    void *p_xq, *p_w1, *p_w2, *p_w3, *p_hq;
    cudaGetSymbolAddress(&p_xq, g_xq);
    cudaGetSymbolAddress(&p_w1, g_w1q);
    cudaGetSymbolAddress(&p_w2, g_w2q);
    cudaGetSymbolAddress(&p_w3, g_w3q);
    cudaGetSymbolAddress(&p_hq, g_hq);

    CUtensorMap tm_xq, tm_w1, tm_w2, tm_w3, tm_hq;
    make_map(enc, &tm_xq, p_xq, DDIM, MTOK);
    make_map(enc, &tm_w1, p_w1, DDIM, HDIM);
    make_map(enc, &tm_w2, p_w2, DDIM, HDIM);
    make_map(enc, &tm_w3, p_w3, HDIM, DDIM);
    make_map(enc, &tm_hq, p_hq, HDIM, MTOK);

    const int nW = HDIM * DDIM;
    wsum_partial_all<<<3072, 256>>>(w1, w2, w3, nW);
    wsum_final_all<<<3, 256>>>(nW);
    dim3 gq((nW + 255) / 256, 3);
    wquant_all<<<gq, 256>>>(w1, w2, w3, nW);

    // x -> rmsnorm -> int8
    actq_x<<<MTOK, 256>>>(x);

    // gate = xq @ w1q^T, up = xq @ w2q^T   [MTOK, HDIM]
    dim3 g1(HDIM / BN, MTOK / BM);
    gemm_s8<<<g1, 256>>>(0, nullptr, HDIM, DDIM, tm_xq, tm_w1);
    gemm_s8<<<g1, 256>>>(1, nullptr, HDIM, DDIM, tm_xq, tm_w2);

    // h = silu(gate)*up -> rmsnorm -> int8 (fused)
    actq_h<<<MTOK, 256>>>();

    // out = hq @ w3q^T  [MTOK, DDIM]
    dim3 g3(DDIM / BN, MTOK / BM);
    gemm_s8<<<g3, 256>>>(2, out, DDIM, HDIM, tm_hq, tm_w3);
}